// round 10
// baseline (speedup 1.0000x reference)
#include <cuda_runtime.h>
#include <cstdint>

#define NB 32
#define NT 512
#define ND 512
#define NH 1024
#define NM (NB*NT)   // 16384 rows

typedef unsigned long long ull;

// ---- scratch (device globals; no runtime allocation allowed) ----
__device__ float         g_h1[(size_t)NM * NH];   // 64 MB fc1 raw output
__device__ unsigned char g_s1[(size_t)NM * NH];   // 16 MB spikes layer 1
__device__ float         g_y [(size_t)NM * ND];   // 32 MB fc2+ln2 out
__device__ float         g_w2t[(size_t)NH * ND];  //  2 MB w2 transposed to [H, D]
__device__ float         g_mean[NM];              // ln1 row means
__device__ float         g_inv [NM];              // ln1 row inv-std

// ---- packed fp32x2 helpers (Blackwell FFMA2, identical per-lane fp32 rounding) ----
__device__ __forceinline__ ull pack2(float lo, float hi) {
    ull r;
    asm("mov.b64 %0, {%1, %2};" : "=l"(r)
        : "r"(__float_as_uint(lo)), "r"(__float_as_uint(hi)));
    return r;
}
__device__ __forceinline__ void unpack2(ull v, float& lo, float& hi) {
    unsigned a, b;
    asm("mov.b64 {%0, %1}, %2;" : "=r"(a), "=r"(b) : "l"(v));
    lo = __uint_as_float(a); hi = __uint_as_float(b);
}
__device__ __forceinline__ ull fma2(ull a, ull b, ull c) {
    ull d;
    asm("fma.rn.f32x2 %0, %1, %2, %3;" : "=l"(d) : "l"(a), "l"(b), "l"(c));
    return d;
}

// ============================================================================
// GEMM1: g_h1[m,n] = sum_k x[m,k]*w1[n,k] + b1[n]   (ascending-k, bitwise-exact)
// R4 structure; change: A tile stored in smem PRE-DUPLICATED as (a,a) ull pairs
// -> inner loop has zero MOVs, fma2 fed directly by broadcast LDS.64.
// ============================================================================
__global__ __launch_bounds__(256) void gemm1_kernel(const float* __restrict__ A,
                                                    const float* __restrict__ W,
                                                    const float* __restrict__ bias) {
    __shared__ __align__(16) ull   Asd[16][132];   // (a,a) pairs, 16.9 KB
    __shared__ __align__(16) float Bs[16][132];
    const int tid  = threadIdx.x;
    const int row0 = blockIdx.y * 128;
    const int col0 = blockIdx.x * 128;
    const int tx = tid & 15;
    const int ty = tid >> 4;
    const int lm = tid >> 2;
    const int lk = (tid & 3) * 4;

    const float* Ap = A + (size_t)(row0 + lm) * ND + lk;
    const float* Bp = W + (size_t)(col0 + lm) * ND + lk;

    ull acc[8][4];
#pragma unroll
    for (int i = 0; i < 8; i++)
#pragma unroll
        for (int j = 0; j < 4; j++) acc[i][j] = 0ull;

    float4 pa0 = *(const float4*)(Ap);
    float4 pa1 = *(const float4*)(Ap + (size_t)64 * ND);
    float4 pb0 = *(const float4*)(Bp);
    float4 pb1 = *(const float4*)(Bp + (size_t)64 * ND);

#pragma unroll 1
    for (int kt = 0; kt < 32; kt++) {
        Asd[lk + 0][lm] = pack2(pa0.x, pa0.x);
        Asd[lk + 1][lm] = pack2(pa0.y, pa0.y);
        Asd[lk + 2][lm] = pack2(pa0.z, pa0.z);
        Asd[lk + 3][lm] = pack2(pa0.w, pa0.w);
        Asd[lk + 0][lm + 64] = pack2(pa1.x, pa1.x);
        Asd[lk + 1][lm + 64] = pack2(pa1.y, pa1.y);
        Asd[lk + 2][lm + 64] = pack2(pa1.z, pa1.z);
        Asd[lk + 3][lm + 64] = pack2(pa1.w, pa1.w);
        Bs[lk + 0][lm] = pb0.x; Bs[lk + 1][lm] = pb0.y; Bs[lk + 2][lm] = pb0.z; Bs[lk + 3][lm] = pb0.w;
        Bs[lk + 0][lm + 64] = pb1.x; Bs[lk + 1][lm + 64] = pb1.y; Bs[lk + 2][lm + 64] = pb1.z; Bs[lk + 3][lm + 64] = pb1.w;
        __syncthreads();

        if (kt < 31) {
            const float* Ap2 = Ap + (kt + 1) * 16;
            const float* Bp2 = Bp + (kt + 1) * 16;
            pa0 = *(const float4*)(Ap2);
            pa1 = *(const float4*)(Ap2 + (size_t)64 * ND);
            pb0 = *(const float4*)(Bp2);
            pb1 = *(const float4*)(Bp2 + (size_t)64 * ND);
        }

#pragma unroll
        for (int kk = 0; kk < 16; kk++) {
            ulonglong2 bl0 = *(const ulonglong2*)&Bs[kk][tx * 8];
            ulonglong2 bl1 = *(const ulonglong2*)&Bs[kk][tx * 8 + 4];
#pragma unroll
            for (int i = 0; i < 8; i++) {
                ull aa = Asd[kk][ty * 8 + i];
                acc[i][0] = fma2(aa, bl0.x, acc[i][0]);
                acc[i][1] = fma2(aa, bl0.y, acc[i][1]);
                acc[i][2] = fma2(aa, bl1.x, acc[i][2]);
                acc[i][3] = fma2(aa, bl1.y, acc[i][3]);
            }
        }
        __syncthreads();
    }

    float bv[8];
#pragma unroll
    for (int j = 0; j < 8; j++) bv[j] = bias[col0 + tx * 8 + j];
#pragma unroll
    for (int i = 0; i < 8; i++) {
        float o[8];
        unpack2(acc[i][0], o[0], o[1]);
        unpack2(acc[i][1], o[2], o[3]);
        unpack2(acc[i][2], o[4], o[5]);
        unpack2(acc[i][3], o[6], o[7]);
#pragma unroll
        for (int j = 0; j < 8; j++) o[j] += bv[j];
        float* cp = g_h1 + (size_t)(row0 + ty * 8 + i) * NH + col0 + tx * 8;
        ((float4*)cp)[0] = make_float4(o[0], o[1], o[2], o[3]);
        ((float4*)cp)[1] = make_float4(o[4], o[5], o[6], o[7]);
    }
}

// ============================================================================
// block-wide reduction (blockDim multiple of 32, <= 256)
// ============================================================================
__device__ __forceinline__ float block_reduce_sum(float val) {
    __shared__ float sm[32];
    const int tid = threadIdx.x;
#pragma unroll
    for (int o = 16; o; o >>= 1) val += __shfl_down_sync(0xffffffffu, val, o);
    if ((tid & 31) == 0) sm[tid >> 5] = val;
    __syncthreads();
    if (tid < 32) {
        const int nw = (blockDim.x + 31) >> 5;
        float v = (tid < nw) ? sm[tid] : 0.f;
#pragma unroll
        for (int o = 4; o; o >>= 1) v += __shfl_down_sync(0xffffffffu, v, o);
        if (tid == 0) sm[0] = v;
    }
    __syncthreads();
    float r = sm[0];
    __syncthreads();
    return r;
}

// ============================================================================
// LN1 stats only: mean & inv-std per row of g_h1.
// ============================================================================
__global__ __launch_bounds__(256) void ln1_stats_kernel() {
    const float* p = g_h1 + (size_t)blockIdx.x * NH;
    const int tid = threadIdx.x;
    float4 v = ((const float4*)p)[tid];
    float s = (v.x + v.y) + (v.z + v.w);
    float total = block_reduce_sum(s);
    float mean = total * (1.0f / NH);
    float d0 = v.x - mean, d1 = v.y - mean, d2 = v.z - mean, d3 = v.w - mean;
    float sq = (d0 * d0 + d1 * d1) + (d2 * d2 + d3 * d3);
    float tot2 = block_reduce_sum(sq);
    float inv = 1.0f / sqrtf(tot2 * (1.0f / NH) + 1e-5f);
    if (tid == 0) { g_mean[blockIdx.x] = mean; g_inv[blockIdx.x] = inv; }
}

// ============================================================================
// LIF layer 1 with inline LayerNorm (R4-verified byte-spike version).
// ============================================================================
__global__ __launch_bounds__(128) void lif1_kernel(const float* __restrict__ g1,
                                                   const float* __restrict__ be1) {
    const int idx = blockIdx.x * 128 + threadIdx.x;   // NB*NH = 32768
    const int b = idx >> 10;
    const int h = idx & (NH - 1);
    const int tid = threadIdx.x;

    __shared__ float s_mean[NT];
    __shared__ float s_inv[NT];
#pragma unroll
    for (int t = tid; t < NT; t += 128) {
        s_mean[t] = g_mean[b * NT + t];
        s_inv[t]  = g_inv [b * NT + t];
    }
    __syncthreads();

    const float gh  = g1[h];
    const float beh = be1[h];
    const float* p = g_h1 + (size_t)b * NT * NH + h;
    unsigned char* q = g_s1 + (size_t)b * NT * NH + h;
    float v = 0.f;
#pragma unroll 1
    for (int t0 = 0; t0 < NT; t0 += 16) {
        float xb[16];
#pragma unroll
        for (int i = 0; i < 16; i++) xb[i] = p[(size_t)(t0 + i) * NH];
        unsigned char sb[16];
#pragma unroll
        for (int i = 0; i < 16; i++) {
            float d = xb[i] - s_mean[t0 + i];
            float val = d * s_inv[t0 + i] * gh + beh;
            v = v + (val - v) * 0.5f;       // TAU = 2
            bool sp = (v >= 1.0f);          // V_TH = 1
            sb[i] = sp ? (unsigned char)1 : (unsigned char)0;
            v = sp ? 0.f : v;               // hard reset
        }
#pragma unroll
        for (int i = 0; i < 16; i++) q[(size_t)(t0 + i) * NH] = sb[i];
    }
}

// ============================================================================
// fc2 (sparse gmem gather, L1-resident w2t) + fused LayerNorm2 (R4-verified).
// ============================================================================
__global__ __launch_bounds__(128) void fc2ln2_kernel(const float* __restrict__ b2,
                                                     const float* __restrict__ g2,
                                                     const float* __restrict__ be2) {
    const int row = blockIdx.x;
    const int tid = threadIdx.x;
    const unsigned char* srow = g_s1 + (size_t)row * NH;

    ull m8 = ((const ull*)srow)[tid];           // 8 spike bytes
    int c = __popcll(m8);
    int pre = c;
#pragma unroll
    for (int o = 1; o < 32; o <<= 1) {
        int n = __shfl_up_sync(0xffffffffu, pre, o);
        if ((tid & 31) >= o) pre += n;
    }
    __shared__ int wsum[4];
    __shared__ unsigned short list[NH];
    __shared__ int s_total;
    if ((tid & 31) == 31) wsum[tid >> 5] = pre;
    __syncthreads();
    int base = 0;
#pragma unroll
    for (int w = 0; w < 4; w++)
        if (w < (tid >> 5)) base += wsum[w];
    int off = base + pre - c;
#pragma unroll
    for (int k = 0; k < 8; k++)
        if ((m8 >> (8 * k)) & 1ull) list[off++] = (unsigned short)(tid * 8 + k);
    if (tid == 127) s_total = base + pre;
    __syncthreads();

    const int cnt = s_total;
    const float* wbase = g_w2t + tid * 4;
    float4 acc = make_float4(0.f, 0.f, 0.f, 0.f);
    int i = 0;
    for (; i + 4 <= cnt; i += 4) {
        int h0 = list[i], h1 = list[i + 1], h2 = list[i + 2], h3 = list[i + 3];
        float4 w0 = *(const float4*)(wbase + (size_t)h0 * ND);
        float4 w1 = *(const float4*)(wbase + (size_t)h1 * ND);
        float4 w2v = *(const float4*)(wbase + (size_t)h2 * ND);
        float4 w3 = *(const float4*)(wbase + (size_t)h3 * ND);
        acc.x += w0.x; acc.y += w0.y; acc.z += w0.z; acc.w += w0.w;
        acc.x += w1.x; acc.y += w1.y; acc.z += w1.z; acc.w += w1.w;
        acc.x += w2v.x; acc.y += w2v.y; acc.z += w2v.z; acc.w += w2v.w;
        acc.x += w3.x; acc.y += w3.y; acc.z += w3.z; acc.w += w3.w;
    }
    for (; i < cnt; i++) {
        float4 w0 = *(const float4*)(wbase + (size_t)list[i] * ND);
        acc.x += w0.x; acc.y += w0.y; acc.z += w0.z; acc.w += w0.w;
    }
    float4 bb = ((const float4*)b2)[tid];
    acc.x += bb.x; acc.y += bb.y; acc.z += bb.z; acc.w += bb.w;

    // ---- fused LayerNorm2 ----
    float s = (acc.x + acc.y) + (acc.z + acc.w);
    float total = block_reduce_sum(s);
    float mean = total * (1.0f / ND);
    float d0 = acc.x - mean, d1 = acc.y - mean, d2 = acc.z - mean, d3 = acc.w - mean;
    float sq = (d0 * d0 + d1 * d1) + (d2 * d2 + d3 * d3);
    float tot2 = block_reduce_sum(sq);
    float inv = 1.0f / sqrtf(tot2 * (1.0f / ND) + 1e-5f);
    float4 gg = ((const float4*)g2)[tid];
    float4 bv = ((const float4*)be2)[tid];
    float4 o;
    o.x = d0 * inv * gg.x + bv.x;
    o.y = d1 * inv * gg.y + bv.y;
    o.z = d2 * inv * gg.z + bv.z;
    o.w = d3 * inv * gg.w + bv.w;
    ((float4*)(g_y + (size_t)row * ND))[tid] = o;
}

// ============================================================================
// LIF layer 2 + residual (R4-verified 16-deep config): out = x + spike2.
// ============================================================================
__global__ __launch_bounds__(64) void lif2_kernel(const float* __restrict__ x,
                                                  float* __restrict__ out) {
    const int idx = blockIdx.x * 64 + threadIdx.x;    // NB*ND = 16384
    const int b = idx >> 9;
    const int d = idx & (ND - 1);
    const float* py = g_y + (size_t)b * NT * ND + d;
    const float* px = x + (size_t)b * NT * ND + d;
    float* po = out + (size_t)b * NT * ND + d;
    float v = 0.f;
#pragma unroll 1
    for (int t0 = 0; t0 < NT; t0 += 16) {
        float yb[16], xb[16];
#pragma unroll
        for (int i = 0; i < 16; i++) yb[i] = py[(size_t)(t0 + i) * ND];
#pragma unroll
        for (int i = 0; i < 16; i++) xb[i] = px[(size_t)(t0 + i) * ND];
        float ob[16];
#pragma unroll
        for (int i = 0; i < 16; i++) {
            v = v + (yb[i] - v) * 0.5f;
            bool sp = (v >= 1.0f);
            ob[i] = xb[i] + (sp ? 1.0f : 0.0f);
            v = sp ? 0.f : v;
        }
#pragma unroll
        for (int i = 0; i < 16; i++) po[(size_t)(t0 + i) * ND] = ob[i];
    }
}

// ============================================================================
// w2 [D, H] -> g_w2t [H, D]
// ============================================================================
__global__ void transpose_kernel(const float* __restrict__ w2) {
    __shared__ float tile[32][33];
    const int h0 = blockIdx.x * 32;
    const int d0 = blockIdx.y * 32;
    tile[threadIdx.y][threadIdx.x] = w2[(size_t)(d0 + threadIdx.y) * NH + h0 + threadIdx.x];
    __syncthreads();
    g_w2t[(size_t)(h0 + threadIdx.y) * ND + d0 + threadIdx.x] = tile[threadIdx.x][threadIdx.y];
}

// ============================================================================
extern "C" void kernel_launch(void* const* d_in, const int* in_sizes, int n_in,
                              void* d_out, int out_size) {
    const float* x   = (const float*)d_in[0];
    const float* w1  = (const float*)d_in[1];
    const float* b1  = (const float*)d_in[2];
    const float* g1  = (const float*)d_in[3];
    const float* be1 = (const float*)d_in[4];
    const float* w2  = (const float*)d_in[5];
    const float* b2  = (const float*)d_in[6];
    const float* g2  = (const float*)d_in[7];
    const float* be2 = (const float*)d_in[8];
    float* out = (float*)d_out;

    transpose_kernel<<<dim3(NH / 32, ND / 32), dim3(32, 32)>>>(w2);
    gemm1_kernel<<<dim3(NH / 128, NM / 128), 256>>>(x, w1, b1);
    ln1_stats_kernel<<<NM, 256>>>();
    lif1_kernel<<<(NB * NH) / 128, 128>>>(g1, be1);
    fc2ln2_kernel<<<NM, 128>>>(b2, g2, be2);
    lif2_kernel<<<(NB * ND) / 64, 64>>>(x, out);
}

// round 11
// speedup vs baseline: 1.3154x; 1.3154x over previous
#include <cuda_runtime.h>
#include <cstdint>

#define NB 32
#define NT 512
#define ND 512
#define NH 1024
#define NM (NB*NT)   // 16384 rows

typedef unsigned long long ull;

// ---- scratch (device globals; no runtime allocation allowed) ----
__device__ float         g_h1[(size_t)NM * NH];   // 64 MB fc1 raw output
__device__ unsigned char g_s1[(size_t)NM * NH];   // 16 MB spikes layer 1
__device__ float         g_y [(size_t)NM * ND];   // 32 MB fc2+ln2 out
__device__ float         g_w2t[(size_t)NH * ND];  //  2 MB w2 transposed to [H, D]
__device__ float         g_mean[NM];              // ln1 row means
__device__ float         g_inv [NM];              // ln1 row inv-std

// ---- packed fp32x2 helpers (Blackwell FFMA2, identical per-lane fp32 rounding) ----
__device__ __forceinline__ ull pack2(float lo, float hi) {
    ull r;
    asm("mov.b64 %0, {%1, %2};" : "=l"(r)
        : "r"(__float_as_uint(lo)), "r"(__float_as_uint(hi)));
    return r;
}
__device__ __forceinline__ void unpack2(ull v, float& lo, float& hi) {
    unsigned a, b;
    asm("mov.b64 {%0, %1}, %2;" : "=r"(a), "=r"(b) : "l"(v));
    lo = __uint_as_float(a); hi = __uint_as_float(b);
}
__device__ __forceinline__ ull fma2(ull a, ull b, ull c) {
    ull d;
    asm("fma.rn.f32x2 %0, %1, %2, %3;" : "=l"(d) : "l"(a), "l"(b), "l"(c));
    return d;
}

// ============================================================================
// GEMM1 (R9-verified 535us version): g_h1[m,n] = sum_k x[m,k]*w1[n,k] + b1[n]
// 128x128 tile, BK=16, 256 threads, 8x8/thread, single-buffer smem + reg
// prefetch, ulonglong2 B loads, ascending-k (bitwise-exact).
// ============================================================================
__global__ __launch_bounds__(256) void gemm1_kernel(const float* __restrict__ A,
                                                    const float* __restrict__ W,
                                                    const float* __restrict__ bias) {
    __shared__ __align__(16) float As[16][132];
    __shared__ __align__(16) float Bs[16][132];
    const int tid  = threadIdx.x;
    const int row0 = blockIdx.y * 128;
    const int col0 = blockIdx.x * 128;
    const int tx = tid & 15;
    const int ty = tid >> 4;
    const int lm = tid >> 2;
    const int lk = (tid & 3) * 4;

    const float* Ap = A + (size_t)(row0 + lm) * ND + lk;
    const float* Bp = W + (size_t)(col0 + lm) * ND + lk;

    ull acc[8][4];
#pragma unroll
    for (int i = 0; i < 8; i++)
#pragma unroll
        for (int j = 0; j < 4; j++) acc[i][j] = 0ull;

    float4 pa0 = *(const float4*)(Ap);
    float4 pa1 = *(const float4*)(Ap + (size_t)64 * ND);
    float4 pb0 = *(const float4*)(Bp);
    float4 pb1 = *(const float4*)(Bp + (size_t)64 * ND);

#pragma unroll 1
    for (int kt = 0; kt < 32; kt++) {
        As[lk + 0][lm] = pa0.x; As[lk + 1][lm] = pa0.y; As[lk + 2][lm] = pa0.z; As[lk + 3][lm] = pa0.w;
        As[lk + 0][lm + 64] = pa1.x; As[lk + 1][lm + 64] = pa1.y; As[lk + 2][lm + 64] = pa1.z; As[lk + 3][lm + 64] = pa1.w;
        Bs[lk + 0][lm] = pb0.x; Bs[lk + 1][lm] = pb0.y; Bs[lk + 2][lm] = pb0.z; Bs[lk + 3][lm] = pb0.w;
        Bs[lk + 0][lm + 64] = pb1.x; Bs[lk + 1][lm + 64] = pb1.y; Bs[lk + 2][lm + 64] = pb1.z; Bs[lk + 3][lm + 64] = pb1.w;
        __syncthreads();

        if (kt < 31) {
            const float* Ap2 = Ap + (kt + 1) * 16;
            const float* Bp2 = Bp + (kt + 1) * 16;
            pa0 = *(const float4*)(Ap2);
            pa1 = *(const float4*)(Ap2 + (size_t)64 * ND);
            pb0 = *(const float4*)(Bp2);
            pb1 = *(const float4*)(Bp2 + (size_t)64 * ND);
        }

#pragma unroll
        for (int kk = 0; kk < 16; kk++) {
            float4 a0 = *(const float4*)&As[kk][ty * 8];
            float4 a1 = *(const float4*)&As[kk][ty * 8 + 4];
            ulonglong2 bl0 = *(const ulonglong2*)&Bs[kk][tx * 8];
            ulonglong2 bl1 = *(const ulonglong2*)&Bs[kk][tx * 8 + 4];
            float av[8] = {a0.x, a0.y, a0.z, a0.w, a1.x, a1.y, a1.z, a1.w};
#pragma unroll
            for (int i = 0; i < 8; i++) {
                ull aa = pack2(av[i], av[i]);
                acc[i][0] = fma2(aa, bl0.x, acc[i][0]);
                acc[i][1] = fma2(aa, bl0.y, acc[i][1]);
                acc[i][2] = fma2(aa, bl1.x, acc[i][2]);
                acc[i][3] = fma2(aa, bl1.y, acc[i][3]);
            }
        }
        __syncthreads();
    }

    float bv[8];
#pragma unroll
    for (int j = 0; j < 8; j++) bv[j] = bias[col0 + tx * 8 + j];
#pragma unroll
    for (int i = 0; i < 8; i++) {
        float o[8];
        unpack2(acc[i][0], o[0], o[1]);
        unpack2(acc[i][1], o[2], o[3]);
        unpack2(acc[i][2], o[4], o[5]);
        unpack2(acc[i][3], o[6], o[7]);
#pragma unroll
        for (int j = 0; j < 8; j++) o[j] += bv[j];
        float* cp = g_h1 + (size_t)(row0 + ty * 8 + i) * NH + col0 + tx * 8;
        ((float4*)cp)[0] = make_float4(o[0], o[1], o[2], o[3]);
        ((float4*)cp)[1] = make_float4(o[4], o[5], o[6], o[7]);
    }
}

// ============================================================================
// block-wide reduction (blockDim multiple of 32, <= 256)
// ============================================================================
__device__ __forceinline__ float block_reduce_sum(float val) {
    __shared__ float sm[32];
    const int tid = threadIdx.x;
#pragma unroll
    for (int o = 16; o; o >>= 1) val += __shfl_down_sync(0xffffffffu, val, o);
    if ((tid & 31) == 0) sm[tid >> 5] = val;
    __syncthreads();
    if (tid < 32) {
        const int nw = (blockDim.x + 31) >> 5;
        float v = (tid < nw) ? sm[tid] : 0.f;
#pragma unroll
        for (int o = 4; o; o >>= 1) v += __shfl_down_sync(0xffffffffu, v, o);
        if (tid == 0) sm[0] = v;
    }
    __syncthreads();
    float r = sm[0];
    __syncthreads();
    return r;
}

// ============================================================================
// LN1 stats only: mean & inv-std per row of g_h1.
// ============================================================================
__global__ __launch_bounds__(256) void ln1_stats_kernel() {
    const float* p = g_h1 + (size_t)blockIdx.x * NH;
    const int tid = threadIdx.x;
    float4 v = ((const float4*)p)[tid];
    float s = (v.x + v.y) + (v.z + v.w);
    float total = block_reduce_sum(s);
    float mean = total * (1.0f / NH);
    float d0 = v.x - mean, d1 = v.y - mean, d2 = v.z - mean, d3 = v.w - mean;
    float sq = (d0 * d0 + d1 * d1) + (d2 * d2 + d3 * d3);
    float tot2 = block_reduce_sum(sq);
    float inv = 1.0f / sqrtf(tot2 * (1.0f / NH) + 1e-5f);
    if (tid == 0) { g_mean[blockIdx.x] = mean; g_inv[blockIdx.x] = inv; }
}

// ============================================================================
// LIF layer 1 with inline LayerNorm (R4-verified byte-spike version).
// ============================================================================
__global__ __launch_bounds__(128) void lif1_kernel(const float* __restrict__ g1,
                                                   const float* __restrict__ be1) {
    const int idx = blockIdx.x * 128 + threadIdx.x;   // NB*NH = 32768
    const int b = idx >> 10;
    const int h = idx & (NH - 1);
    const int tid = threadIdx.x;

    __shared__ float s_mean[NT];
    __shared__ float s_inv[NT];
#pragma unroll
    for (int t = tid; t < NT; t += 128) {
        s_mean[t] = g_mean[b * NT + t];
        s_inv[t]  = g_inv [b * NT + t];
    }
    __syncthreads();

    const float gh  = g1[h];
    const float beh = be1[h];
    const float* p = g_h1 + (size_t)b * NT * NH + h;
    unsigned char* q = g_s1 + (size_t)b * NT * NH + h;
    float v = 0.f;
#pragma unroll 1
    for (int t0 = 0; t0 < NT; t0 += 16) {
        float xb[16];
#pragma unroll
        for (int i = 0; i < 16; i++) xb[i] = p[(size_t)(t0 + i) * NH];
        unsigned char sb[16];
#pragma unroll
        for (int i = 0; i < 16; i++) {
            float d = xb[i] - s_mean[t0 + i];
            float val = d * s_inv[t0 + i] * gh + beh;
            v = v + (val - v) * 0.5f;       // TAU = 2
            bool sp = (v >= 1.0f);          // V_TH = 1
            sb[i] = sp ? (unsigned char)1 : (unsigned char)0;
            v = sp ? 0.f : v;               // hard reset
        }
#pragma unroll
        for (int i = 0; i < 16; i++) q[(size_t)(t0 + i) * NH] = sb[i];
    }
}

// ============================================================================
// fc2 (sparse gmem gather, L1-resident w2t) + fused LayerNorm2 (R4-verified).
// ============================================================================
__global__ __launch_bounds__(128) void fc2ln2_kernel(const float* __restrict__ b2,
                                                     const float* __restrict__ g2,
                                                     const float* __restrict__ be2) {
    const int row = blockIdx.x;
    const int tid = threadIdx.x;
    const unsigned char* srow = g_s1 + (size_t)row * NH;

    ull m8 = ((const ull*)srow)[tid];           // 8 spike bytes
    int c = __popcll(m8);
    int pre = c;
#pragma unroll
    for (int o = 1; o < 32; o <<= 1) {
        int n = __shfl_up_sync(0xffffffffu, pre, o);
        if ((tid & 31) >= o) pre += n;
    }
    __shared__ int wsum[4];
    __shared__ unsigned short list[NH];
    __shared__ int s_total;
    if ((tid & 31) == 31) wsum[tid >> 5] = pre;
    __syncthreads();
    int base = 0;
#pragma unroll
    for (int w = 0; w < 4; w++)
        if (w < (tid >> 5)) base += wsum[w];
    int off = base + pre - c;
#pragma unroll
    for (int k = 0; k < 8; k++)
        if ((m8 >> (8 * k)) & 1ull) list[off++] = (unsigned short)(tid * 8 + k);
    if (tid == 127) s_total = base + pre;
    __syncthreads();

    const int cnt = s_total;
    const float* wbase = g_w2t + tid * 4;
    float4 acc = make_float4(0.f, 0.f, 0.f, 0.f);
    int i = 0;
    for (; i + 4 <= cnt; i += 4) {
        int h0 = list[i], h1 = list[i + 1], h2 = list[i + 2], h3 = list[i + 3];
        float4 w0 = *(const float4*)(wbase + (size_t)h0 * ND);
        float4 w1 = *(const float4*)(wbase + (size_t)h1 * ND);
        float4 w2v = *(const float4*)(wbase + (size_t)h2 * ND);
        float4 w3 = *(const float4*)(wbase + (size_t)h3 * ND);
        acc.x += w0.x; acc.y += w0.y; acc.z += w0.z; acc.w += w0.w;
        acc.x += w1.x; acc.y += w1.y; acc.z += w1.z; acc.w += w1.w;
        acc.x += w2v.x; acc.y += w2v.y; acc.z += w2v.z; acc.w += w2v.w;
        acc.x += w3.x; acc.y += w3.y; acc.z += w3.z; acc.w += w3.w;
    }
    for (; i < cnt; i++) {
        float4 w0 = *(const float4*)(wbase + (size_t)list[i] * ND);
        acc.x += w0.x; acc.y += w0.y; acc.z += w0.z; acc.w += w0.w;
    }
    float4 bb = ((const float4*)b2)[tid];
    acc.x += bb.x; acc.y += bb.y; acc.z += bb.z; acc.w += bb.w;

    // ---- fused LayerNorm2 ----
    float s = (acc.x + acc.y) + (acc.z + acc.w);
    float total = block_reduce_sum(s);
    float mean = total * (1.0f / ND);
    float d0 = acc.x - mean, d1 = acc.y - mean, d2 = acc.z - mean, d3 = acc.w - mean;
    float sq = (d0 * d0 + d1 * d1) + (d2 * d2 + d3 * d3);
    float tot2 = block_reduce_sum(sq);
    float inv = 1.0f / sqrtf(tot2 * (1.0f / ND) + 1e-5f);
    float4 gg = ((const float4*)g2)[tid];
    float4 bv = ((const float4*)be2)[tid];
    float4 o;
    o.x = d0 * inv * gg.x + bv.x;
    o.y = d1 * inv * gg.y + bv.y;
    o.z = d2 * inv * gg.z + bv.z;
    o.w = d3 * inv * gg.w + bv.w;
    ((float4*)(g_y + (size_t)row * ND))[tid] = o;
}

// ============================================================================
// LIF layer 2 + residual, SOFTWARE-PIPELINED: loads of chunk t0+16 issued
// before compute of chunk t0 (double-buffered registers, compile-time
// indices). Per-element arithmetic order identical -> bitwise-exact.
// ============================================================================
__global__ __launch_bounds__(64) void lif2_kernel(const float* __restrict__ x,
                                                  float* __restrict__ out) {
    const int idx = blockIdx.x * 64 + threadIdx.x;    // NB*ND = 16384
    const int b = idx >> 9;
    const int d = idx & (ND - 1);
    const float* py = g_y + (size_t)b * NT * ND + d;
    const float* px = x + (size_t)b * NT * ND + d;
    float* po = out + (size_t)b * NT * ND + d;

    float ya[16], xa[16], yb[16], xb[16];
    // preload chunk 0 into buffer A
#pragma unroll
    for (int i = 0; i < 16; i++) { ya[i] = py[(size_t)i * ND]; }
#pragma unroll
    for (int i = 0; i < 16; i++) { xa[i] = px[(size_t)i * ND]; }

    float v = 0.f;
#pragma unroll 1
    for (int t0 = 0; t0 < NT; t0 += 32) {
        // prefetch chunk t0+16 into buffer B (always exists: t0+16 <= 496)
#pragma unroll
        for (int i = 0; i < 16; i++) yb[i] = py[(size_t)(t0 + 16 + i) * ND];
#pragma unroll
        for (int i = 0; i < 16; i++) xb[i] = px[(size_t)(t0 + 16 + i) * ND];

        // compute + store chunk t0 from buffer A
        float ob[16];
#pragma unroll
        for (int i = 0; i < 16; i++) {
            v = v + (ya[i] - v) * 0.5f;
            bool sp = (v >= 1.0f);
            ob[i] = xa[i] + (sp ? 1.0f : 0.0f);
            v = sp ? 0.f : v;
        }
#pragma unroll
        for (int i = 0; i < 16; i++) po[(size_t)(t0 + i) * ND] = ob[i];

        // prefetch chunk t0+32 into buffer A (skip on last iteration)
        if (t0 + 32 < NT) {
#pragma unroll
            for (int i = 0; i < 16; i++) ya[i] = py[(size_t)(t0 + 32 + i) * ND];
#pragma unroll
            for (int i = 0; i < 16; i++) xa[i] = px[(size_t)(t0 + 32 + i) * ND];
        }

        // compute + store chunk t0+16 from buffer B
#pragma unroll
        for (int i = 0; i < 16; i++) {
            v = v + (yb[i] - v) * 0.5f;
            bool sp = (v >= 1.0f);
            ob[i] = xb[i] + (sp ? 1.0f : 0.0f);
            v = sp ? 0.f : v;
        }
#pragma unroll
        for (int i = 0; i < 16; i++) po[(size_t)(t0 + 16 + i) * ND] = ob[i];
    }
}

// ============================================================================
// w2 [D, H] -> g_w2t [H, D]
// ============================================================================
__global__ void transpose_kernel(const float* __restrict__ w2) {
    __shared__ float tile[32][33];
    const int h0 = blockIdx.x * 32;
    const int d0 = blockIdx.y * 32;
    tile[threadIdx.y][threadIdx.x] = w2[(size_t)(d0 + threadIdx.y) * NH + h0 + threadIdx.x];
    __syncthreads();
    g_w2t[(size_t)(h0 + threadIdx.y) * ND + d0 + threadIdx.x] = tile[threadIdx.x][threadIdx.y];
}

// ============================================================================
extern "C" void kernel_launch(void* const* d_in, const int* in_sizes, int n_in,
                              void* d_out, int out_size) {
    const float* x   = (const float*)d_in[0];
    const float* w1  = (const float*)d_in[1];
    const float* b1  = (const float*)d_in[2];
    const float* g1  = (const float*)d_in[3];
    const float* be1 = (const float*)d_in[4];
    const float* w2  = (const float*)d_in[5];
    const float* b2  = (const float*)d_in[6];
    const float* g2  = (const float*)d_in[7];
    const float* be2 = (const float*)d_in[8];
    float* out = (float*)d_out;

    transpose_kernel<<<dim3(NH / 32, ND / 32), dim3(32, 32)>>>(w2);
    gemm1_kernel<<<dim3(NH / 128, NM / 128), 256>>>(x, w1, b1);
    ln1_stats_kernel<<<NM, 256>>>();
    lif1_kernel<<<(NB * NH) / 128, 128>>>(g1, be1);
    fc2ln2_kernel<<<NM, 128>>>(b2, g2, be2);
    lif2_kernel<<<(NB * ND) / 64, 64>>>(x, out);
}

// round 12
// speedup vs baseline: 1.3489x; 1.0255x over previous
#include <cuda_runtime.h>
#include <cstdint>

#define NB 32
#define NT 512
#define ND 512
#define NH 1024
#define NM (NB*NT)   // 16384 rows

typedef unsigned long long ull;

// ---- scratch (device globals; no runtime allocation allowed) ----
__device__ float         g_h1[(size_t)NM * NH];   // 64 MB fc1 raw output
__device__ unsigned char g_s1[(size_t)NM * NH];   // 16 MB spikes layer 1
__device__ float         g_y [(size_t)NM * ND];   // 32 MB fc2+ln2 out
__device__ float         g_w2t[(size_t)NH * ND];  //  2 MB w2 transposed to [H, D]
__device__ float         g_mean[NM];              // ln1 row means
__device__ float         g_inv [NM];              // ln1 row inv-std

// ---- packed fp32x2 helpers (Blackwell FFMA2, identical per-lane fp32 rounding) ----
__device__ __forceinline__ ull pack2(float lo, float hi) {
    ull r;
    asm("mov.b64 %0, {%1, %2};" : "=l"(r)
        : "r"(__float_as_uint(lo)), "r"(__float_as_uint(hi)));
    return r;
}
__device__ __forceinline__ void unpack2(ull v, float& lo, float& hi) {
    unsigned a, b;
    asm("mov.b64 {%0, %1}, %2;" : "=r"(a), "=r"(b) : "l"(v));
    lo = __uint_as_float(a); hi = __uint_as_float(b);
}
__device__ __forceinline__ ull fma2(ull a, ull b, ull c) {
    ull d;
    asm("fma.rn.f32x2 %0, %1, %2, %3;" : "=l"(d) : "l"(a), "l"(b), "l"(c));
    return d;
}

// ============================================================================
// GEMM1: g_h1[m,n] = sum_k x[m,k]*w1[n,k] + b1[n]  (ascending-k, bitwise-exact)
// R9 inner loop; smem statically double-buffered (kt unrolled by 2, literal
// buffer indices) -> 1 sync per kt instead of 2.
// ============================================================================
#define GEMM_STORE(BUF)                                                        \
    do {                                                                       \
        As[BUF][lk + 0][lm] = pa0.x; As[BUF][lk + 1][lm] = pa0.y;              \
        As[BUF][lk + 2][lm] = pa0.z; As[BUF][lk + 3][lm] = pa0.w;              \
        As[BUF][lk + 0][lm + 64] = pa1.x; As[BUF][lk + 1][lm + 64] = pa1.y;    \
        As[BUF][lk + 2][lm + 64] = pa1.z; As[BUF][lk + 3][lm + 64] = pa1.w;    \
        Bs[BUF][lk + 0][lm] = pb0.x; Bs[BUF][lk + 1][lm] = pb0.y;              \
        Bs[BUF][lk + 2][lm] = pb0.z; Bs[BUF][lk + 3][lm] = pb0.w;              \
        Bs[BUF][lk + 0][lm + 64] = pb1.x; Bs[BUF][lk + 1][lm + 64] = pb1.y;    \
        Bs[BUF][lk + 2][lm + 64] = pb1.z; Bs[BUF][lk + 3][lm + 64] = pb1.w;    \
    } while (0)

#define GEMM_LOAD(KT)                                                          \
    do {                                                                       \
        const float* Ap2 = Ap + (KT) * 16;                                     \
        const float* Bp2 = Bp + (KT) * 16;                                     \
        pa0 = *(const float4*)(Ap2);                                           \
        pa1 = *(const float4*)(Ap2 + (size_t)64 * ND);                         \
        pb0 = *(const float4*)(Bp2);                                           \
        pb1 = *(const float4*)(Bp2 + (size_t)64 * ND);                         \
    } while (0)

#define GEMM_COMPUTE(BUF)                                                      \
    _Pragma("unroll")                                                          \
    for (int kk = 0; kk < 16; kk++) {                                          \
        float4 a0 = *(const float4*)&As[BUF][kk][ty * 8];                      \
        float4 a1 = *(const float4*)&As[BUF][kk][ty * 8 + 4];                  \
        ulonglong2 bl0 = *(const ulonglong2*)&Bs[BUF][kk][tx * 8];             \
        ulonglong2 bl1 = *(const ulonglong2*)&Bs[BUF][kk][tx * 8 + 4];         \
        float av[8] = {a0.x, a0.y, a0.z, a0.w, a1.x, a1.y, a1.z, a1.w};        \
        _Pragma("unroll")                                                      \
        for (int i = 0; i < 8; i++) {                                          \
            ull aa = pack2(av[i], av[i]);                                      \
            acc[i][0] = fma2(aa, bl0.x, acc[i][0]);                            \
            acc[i][1] = fma2(aa, bl0.y, acc[i][1]);                            \
            acc[i][2] = fma2(aa, bl1.x, acc[i][2]);                            \
            acc[i][3] = fma2(aa, bl1.y, acc[i][3]);                            \
        }                                                                      \
    }

__global__ __launch_bounds__(256) void gemm1_kernel(const float* __restrict__ A,
                                                    const float* __restrict__ W,
                                                    const float* __restrict__ bias) {
    __shared__ __align__(16) float As[2][16][132];
    __shared__ __align__(16) float Bs[2][16][132];
    const int tid  = threadIdx.x;
    const int row0 = blockIdx.y * 128;
    const int col0 = blockIdx.x * 128;
    const int tx = tid & 15;
    const int ty = tid >> 4;
    const int lm = tid >> 2;
    const int lk = (tid & 3) * 4;

    const float* Ap = A + (size_t)(row0 + lm) * ND + lk;
    const float* Bp = W + (size_t)(col0 + lm) * ND + lk;

    ull acc[8][4];
#pragma unroll
    for (int i = 0; i < 8; i++)
#pragma unroll
        for (int j = 0; j < 4; j++) acc[i][j] = 0ull;

    float4 pa0, pa1, pb0, pb1;
    GEMM_LOAD(0);
    GEMM_STORE(0);
    GEMM_LOAD(1);        // prefetch kt=1 (overlaps the barrier)
    __syncthreads();

#pragma unroll 1
    for (int kt = 0; kt < 32; kt += 2) {
        // ---- first half: buf0 holds kt; regs hold kt+1 ----
        GEMM_STORE(1);                       // buf1 idle (all reads ended at last sync)
        if (kt + 2 < 32) GEMM_LOAD(kt + 2);  // issue early, hide behind compute
        GEMM_COMPUTE(0);
        __syncthreads();
        // ---- second half: buf1 holds kt+1; regs hold kt+2 (if any) ----
        if (kt + 2 < 32) {
            GEMM_STORE(0);
            if (kt + 3 < 32) GEMM_LOAD(kt + 3);
        }
        GEMM_COMPUTE(1);
        __syncthreads();
    }

    float bv[8];
#pragma unroll
    for (int j = 0; j < 8; j++) bv[j] = bias[col0 + tx * 8 + j];
#pragma unroll
    for (int i = 0; i < 8; i++) {
        float o[8];
        unpack2(acc[i][0], o[0], o[1]);
        unpack2(acc[i][1], o[2], o[3]);
        unpack2(acc[i][2], o[4], o[5]);
        unpack2(acc[i][3], o[6], o[7]);
#pragma unroll
        for (int j = 0; j < 8; j++) o[j] += bv[j];
        float* cp = g_h1 + (size_t)(row0 + ty * 8 + i) * NH + col0 + tx * 8;
        ((float4*)cp)[0] = make_float4(o[0], o[1], o[2], o[3]);
        ((float4*)cp)[1] = make_float4(o[4], o[5], o[6], o[7]);
    }
}

// ============================================================================
// block-wide reduction (blockDim multiple of 32, <= 256)
// ============================================================================
__device__ __forceinline__ float block_reduce_sum(float val) {
    __shared__ float sm[32];
    const int tid = threadIdx.x;
#pragma unroll
    for (int o = 16; o; o >>= 1) val += __shfl_down_sync(0xffffffffu, val, o);
    if ((tid & 31) == 0) sm[tid >> 5] = val;
    __syncthreads();
    if (tid < 32) {
        const int nw = (blockDim.x + 31) >> 5;
        float v = (tid < nw) ? sm[tid] : 0.f;
#pragma unroll
        for (int o = 4; o; o >>= 1) v += __shfl_down_sync(0xffffffffu, v, o);
        if (tid == 0) sm[0] = v;
    }
    __syncthreads();
    float r = sm[0];
    __syncthreads();
    return r;
}

// ============================================================================
// LN1 stats only: mean & inv-std per row of g_h1.
// ============================================================================
__global__ __launch_bounds__(256) void ln1_stats_kernel() {
    const float* p = g_h1 + (size_t)blockIdx.x * NH;
    const int tid = threadIdx.x;
    float4 v = ((const float4*)p)[tid];
    float s = (v.x + v.y) + (v.z + v.w);
    float total = block_reduce_sum(s);
    float mean = total * (1.0f / NH);
    float d0 = v.x - mean, d1 = v.y - mean, d2 = v.z - mean, d3 = v.w - mean;
    float sq = (d0 * d0 + d1 * d1) + (d2 * d2 + d3 * d3);
    float tot2 = block_reduce_sum(sq);
    float inv = 1.0f / sqrtf(tot2 * (1.0f / NH) + 1e-5f);
    if (tid == 0) { g_mean[blockIdx.x] = mean; g_inv[blockIdx.x] = inv; }
}

// ============================================================================
// LIF layer 1 with inline LayerNorm, SOFTWARE-PIPELINED (lif2-style double
// register buffer; per-element arithmetic identical -> bitwise-exact).
// ============================================================================
__global__ __launch_bounds__(128) void lif1_kernel(const float* __restrict__ g1,
                                                   const float* __restrict__ be1) {
    const int idx = blockIdx.x * 128 + threadIdx.x;   // NB*NH = 32768
    const int b = idx >> 10;
    const int h = idx & (NH - 1);
    const int tid = threadIdx.x;

    __shared__ float s_mean[NT];
    __shared__ float s_inv[NT];
#pragma unroll
    for (int t = tid; t < NT; t += 128) {
        s_mean[t] = g_mean[b * NT + t];
        s_inv[t]  = g_inv [b * NT + t];
    }
    __syncthreads();

    const float gh  = g1[h];
    const float beh = be1[h];
    const float* p = g_h1 + (size_t)b * NT * NH + h;
    unsigned char* q = g_s1 + (size_t)b * NT * NH + h;

    float xa[16], xb[16];
#pragma unroll
    for (int i = 0; i < 16; i++) xa[i] = p[(size_t)i * NH];

    float v = 0.f;
#pragma unroll 1
    for (int t0 = 0; t0 < NT; t0 += 32) {
        // prefetch chunk t0+16
#pragma unroll
        for (int i = 0; i < 16; i++) xb[i] = p[(size_t)(t0 + 16 + i) * NH];

        // compute + store chunk t0 (buffer A)
        unsigned char sb[16];
#pragma unroll
        for (int i = 0; i < 16; i++) {
            float d = xa[i] - s_mean[t0 + i];
            float val = d * s_inv[t0 + i] * gh + beh;
            v = v + (val - v) * 0.5f;       // TAU = 2
            bool sp = (v >= 1.0f);          // V_TH = 1
            sb[i] = sp ? (unsigned char)1 : (unsigned char)0;
            v = sp ? 0.f : v;               // hard reset
        }
#pragma unroll
        for (int i = 0; i < 16; i++) q[(size_t)(t0 + i) * NH] = sb[i];

        // prefetch chunk t0+32
        if (t0 + 32 < NT) {
#pragma unroll
            for (int i = 0; i < 16; i++) xa[i] = p[(size_t)(t0 + 32 + i) * NH];
        }

        // compute + store chunk t0+16 (buffer B)
#pragma unroll
        for (int i = 0; i < 16; i++) {
            float d = xb[i] - s_mean[t0 + 16 + i];
            float val = d * s_inv[t0 + 16 + i] * gh + beh;
            v = v + (val - v) * 0.5f;
            bool sp = (v >= 1.0f);
            sb[i] = sp ? (unsigned char)1 : (unsigned char)0;
            v = sp ? 0.f : v;
        }
#pragma unroll
        for (int i = 0; i < 16; i++) q[(size_t)(t0 + 16 + i) * NH] = sb[i];
    }
}

// ============================================================================
// fc2 (sparse gmem gather, L1-resident w2t) + fused LayerNorm2 (R4-verified).
// ============================================================================
__global__ __launch_bounds__(128) void fc2ln2_kernel(const float* __restrict__ b2,
                                                     const float* __restrict__ g2,
                                                     const float* __restrict__ be2) {
    const int row = blockIdx.x;
    const int tid = threadIdx.x;
    const unsigned char* srow = g_s1 + (size_t)row * NH;

    ull m8 = ((const ull*)srow)[tid];           // 8 spike bytes
    int c = __popcll(m8);
    int pre = c;
#pragma unroll
    for (int o = 1; o < 32; o <<= 1) {
        int n = __shfl_up_sync(0xffffffffu, pre, o);
        if ((tid & 31) >= o) pre += n;
    }
    __shared__ int wsum[4];
    __shared__ unsigned short list[NH];
    __shared__ int s_total;
    if ((tid & 31) == 31) wsum[tid >> 5] = pre;
    __syncthreads();
    int base = 0;
#pragma unroll
    for (int w = 0; w < 4; w++)
        if (w < (tid >> 5)) base += wsum[w];
    int off = base + pre - c;
#pragma unroll
    for (int k = 0; k < 8; k++)
        if ((m8 >> (8 * k)) & 1ull) list[off++] = (unsigned short)(tid * 8 + k);
    if (tid == 127) s_total = base + pre;
    __syncthreads();

    const int cnt = s_total;
    const float* wbase = g_w2t + tid * 4;
    float4 acc = make_float4(0.f, 0.f, 0.f, 0.f);
    int i = 0;
    for (; i + 4 <= cnt; i += 4) {
        int h0 = list[i], h1 = list[i + 1], h2 = list[i + 2], h3 = list[i + 3];
        float4 w0 = *(const float4*)(wbase + (size_t)h0 * ND);
        float4 w1 = *(const float4*)(wbase + (size_t)h1 * ND);
        float4 w2v = *(const float4*)(wbase + (size_t)h2 * ND);
        float4 w3 = *(const float4*)(wbase + (size_t)h3 * ND);
        acc.x += w0.x; acc.y += w0.y; acc.z += w0.z; acc.w += w0.w;
        acc.x += w1.x; acc.y += w1.y; acc.z += w1.z; acc.w += w1.w;
        acc.x += w2v.x; acc.y += w2v.y; acc.z += w2v.z; acc.w += w2v.w;
        acc.x += w3.x; acc.y += w3.y; acc.z += w3.z; acc.w += w3.w;
    }
    for (; i < cnt; i++) {
        float4 w0 = *(const float4*)(wbase + (size_t)list[i] * ND);
        acc.x += w0.x; acc.y += w0.y; acc.z += w0.z; acc.w += w0.w;
    }
    float4 bb = ((const float4*)b2)[tid];
    acc.x += bb.x; acc.y += bb.y; acc.z += bb.z; acc.w += bb.w;

    // ---- fused LayerNorm2 ----
    float s = (acc.x + acc.y) + (acc.z + acc.w);
    float total = block_reduce_sum(s);
    float mean = total * (1.0f / ND);
    float d0 = acc.x - mean, d1 = acc.y - mean, d2 = acc.z - mean, d3 = acc.w - mean;
    float sq = (d0 * d0 + d1 * d1) + (d2 * d2 + d3 * d3);
    float tot2 = block_reduce_sum(sq);
    float inv = 1.0f / sqrtf(tot2 * (1.0f / ND) + 1e-5f);
    float4 gg = ((const float4*)g2)[tid];
    float4 bv = ((const float4*)be2)[tid];
    float4 o;
    o.x = d0 * inv * gg.x + bv.x;
    o.y = d1 * inv * gg.y + bv.y;
    o.z = d2 * inv * gg.z + bv.z;
    o.w = d3 * inv * gg.w + bv.w;
    ((float4*)(g_y + (size_t)row * ND))[tid] = o;
}

// ============================================================================
// LIF layer 2 + residual, SOFTWARE-PIPELINED (R11-verified).
// ============================================================================
__global__ __launch_bounds__(64) void lif2_kernel(const float* __restrict__ x,
                                                  float* __restrict__ out) {
    const int idx = blockIdx.x * 64 + threadIdx.x;    // NB*ND = 16384
    const int b = idx >> 9;
    const int d = idx & (ND - 1);
    const float* py = g_y + (size_t)b * NT * ND + d;
    const float* px = x + (size_t)b * NT * ND + d;
    float* po = out + (size_t)b * NT * ND + d;

    float ya[16], xa[16], yb[16], xb[16];
#pragma unroll
    for (int i = 0; i < 16; i++) { ya[i] = py[(size_t)i * ND]; }
#pragma unroll
    for (int i = 0; i < 16; i++) { xa[i] = px[(size_t)i * ND]; }

    float v = 0.f;
#pragma unroll 1
    for (int t0 = 0; t0 < NT; t0 += 32) {
#pragma unroll
        for (int i = 0; i < 16; i++) yb[i] = py[(size_t)(t0 + 16 + i) * ND];
#pragma unroll
        for (int i = 0; i < 16; i++) xb[i] = px[(size_t)(t0 + 16 + i) * ND];

        float ob[16];
#pragma unroll
        for (int i = 0; i < 16; i++) {
            v = v + (ya[i] - v) * 0.5f;
            bool sp = (v >= 1.0f);
            ob[i] = xa[i] + (sp ? 1.0f : 0.0f);
            v = sp ? 0.f : v;
        }
#pragma unroll
        for (int i = 0; i < 16; i++) po[(size_t)(t0 + i) * ND] = ob[i];

        if (t0 + 32 < NT) {
#pragma unroll
            for (int i = 0; i < 16; i++) ya[i] = py[(size_t)(t0 + 32 + i) * ND];
#pragma unroll
            for (int i = 0; i < 16; i++) xa[i] = px[(size_t)(t0 + 32 + i) * ND];
        }

#pragma unroll
        for (int i = 0; i < 16; i++) {
            v = v + (yb[i] - v) * 0.5f;
            bool sp = (v >= 1.0f);
            ob[i] = xb[i] + (sp ? 1.0f : 0.0f);
            v = sp ? 0.f : v;
        }
#pragma unroll
        for (int i = 0; i < 16; i++) po[(size_t)(t0 + 16 + i) * ND] = ob[i];
    }
}

// ============================================================================
// w2 [D, H] -> g_w2t [H, D]
// ============================================================================
__global__ void transpose_kernel(const float* __restrict__ w2) {
    __shared__ float tile[32][33];
    const int h0 = blockIdx.x * 32;
    const int d0 = blockIdx.y * 32;
    tile[threadIdx.y][threadIdx.x] = w2[(size_t)(d0 + threadIdx.y) * NH + h0 + threadIdx.x];
    __syncthreads();
    g_w2t[(size_t)(h0 + threadIdx.y) * ND + d0 + threadIdx.x] = tile[threadIdx.x][threadIdx.y];
}

// ============================================================================
extern "C" void kernel_launch(void* const* d_in, const int* in_sizes, int n_in,
                              void* d_out, int out_size) {
    const float* x   = (const float*)d_in[0];
    const float* w1  = (const float*)d_in[1];
    const float* b1  = (const float*)d_in[2];
    const float* g1  = (const float*)d_in[3];
    const float* be1 = (const float*)d_in[4];
    const float* w2  = (const float*)d_in[5];
    const float* b2  = (const float*)d_in[6];
    const float* g2  = (const float*)d_in[7];
    const float* be2 = (const float*)d_in[8];
    float* out = (float*)d_out;

    transpose_kernel<<<dim3(NH / 32, ND / 32), dim3(32, 32)>>>(w2);
    gemm1_kernel<<<dim3(NH / 128, NM / 128), 256>>>(x, w1, b1);
    ln1_stats_kernel<<<NM, 256>>>();
    lif1_kernel<<<(NB * NH) / 128, 128>>>(g1, be1);
    fc2ln2_kernel<<<NM, 128>>>(b2, g2, be2);
    lif2_kernel<<<(NB * ND) / 64, 64>>>(x, out);
}

// round 13
// speedup vs baseline: 1.3670x; 1.0134x over previous
#include <cuda_runtime.h>
#include <cstdint>

#define NB 32
#define NT 512
#define ND 512
#define NH 1024
#define NM (NB*NT)   // 16384 rows

typedef unsigned long long ull;

// ---- scratch (device globals; no runtime allocation allowed) ----
__device__ float         g_h1[(size_t)NM * NH];   // 64 MB fc1 raw output
__device__ unsigned char g_s1[(size_t)NM * NH];   // 16 MB spikes layer 1
__device__ float         g_y [(size_t)NM * ND];   // 32 MB fc2+ln2 out
__device__ float         g_w2t[(size_t)NH * ND];  //  2 MB w2 transposed to [H, D]
__device__ float         g_mean[NM];              // ln1 row means
__device__ float         g_inv [NM];              // ln1 row inv-std

// ---- packed fp32x2 helpers (Blackwell FFMA2, identical per-lane fp32 rounding) ----
__device__ __forceinline__ ull pack2(float lo, float hi) {
    ull r;
    asm("mov.b64 %0, {%1, %2};" : "=l"(r)
        : "r"(__float_as_uint(lo)), "r"(__float_as_uint(hi)));
    return r;
}
__device__ __forceinline__ void unpack2(ull v, float& lo, float& hi) {
    unsigned a, b;
    asm("mov.b64 {%0, %1}, %2;" : "=r"(a), "=r"(b) : "l"(v));
    lo = __uint_as_float(a); hi = __uint_as_float(b);
}
__device__ __forceinline__ ull fma2(ull a, ull b, ull c) {
    ull d;
    asm("fma.rn.f32x2 %0, %1, %2, %3;" : "=l"(d) : "l"(a), "l"(b), "l"(c));
    return d;
}

// ============================================================================
// GEMM1: g_h1[m,n] = sum_k x[m,k]*w1[n,k] + b1[n]  (ascending-k, bitwise-exact)
// R12-verified static double-buffer; launch_bounds(256,2) requests 2 blocks/SM.
// ============================================================================
#define GEMM_STORE(BUF)                                                        \
    do {                                                                       \
        As[BUF][lk + 0][lm] = pa0.x; As[BUF][lk + 1][lm] = pa0.y;              \
        As[BUF][lk + 2][lm] = pa0.z; As[BUF][lk + 3][lm] = pa0.w;              \
        As[BUF][lk + 0][lm + 64] = pa1.x; As[BUF][lk + 1][lm + 64] = pa1.y;    \
        As[BUF][lk + 2][lm + 64] = pa1.z; As[BUF][lk + 3][lm + 64] = pa1.w;    \
        Bs[BUF][lk + 0][lm] = pb0.x; Bs[BUF][lk + 1][lm] = pb0.y;              \
        Bs[BUF][lk + 2][lm] = pb0.z; Bs[BUF][lk + 3][lm] = pb0.w;              \
        Bs[BUF][lk + 0][lm + 64] = pb1.x; Bs[BUF][lk + 1][lm + 64] = pb1.y;    \
        Bs[BUF][lk + 2][lm + 64] = pb1.z; Bs[BUF][lk + 3][lm + 64] = pb1.w;    \
    } while (0)

#define GEMM_LOAD(KT)                                                          \
    do {                                                                       \
        const float* Ap2 = Ap + (KT) * 16;                                     \
        const float* Bp2 = Bp + (KT) * 16;                                     \
        pa0 = *(const float4*)(Ap2);                                           \
        pa1 = *(const float4*)(Ap2 + (size_t)64 * ND);                         \
        pb0 = *(const float4*)(Bp2);                                           \
        pb1 = *(const float4*)(Bp2 + (size_t)64 * ND);                         \
    } while (0)

#define GEMM_COMPUTE(BUF)                                                      \
    _Pragma("unroll")                                                          \
    for (int kk = 0; kk < 16; kk++) {                                          \
        float4 a0 = *(const float4*)&As[BUF][kk][ty * 8];                      \
        float4 a1 = *(const float4*)&As[BUF][kk][ty * 8 + 4];                  \
        ulonglong2 bl0 = *(const ulonglong2*)&Bs[BUF][kk][tx * 8];             \
        ulonglong2 bl1 = *(const ulonglong2*)&Bs[BUF][kk][tx * 8 + 4];         \
        float av[8] = {a0.x, a0.y, a0.z, a0.w, a1.x, a1.y, a1.z, a1.w};        \
        _Pragma("unroll")                                                      \
        for (int i = 0; i < 8; i++) {                                          \
            ull aa = pack2(av[i], av[i]);                                      \
            acc[i][0] = fma2(aa, bl0.x, acc[i][0]);                            \
            acc[i][1] = fma2(aa, bl0.y, acc[i][1]);                            \
            acc[i][2] = fma2(aa, bl1.x, acc[i][2]);                            \
            acc[i][3] = fma2(aa, bl1.y, acc[i][3]);                            \
        }                                                                      \
    }

__global__ __launch_bounds__(256, 2) void gemm1_kernel(const float* __restrict__ A,
                                                       const float* __restrict__ W,
                                                       const float* __restrict__ bias) {
    __shared__ __align__(16) float As[2][16][132];
    __shared__ __align__(16) float Bs[2][16][132];
    const int tid  = threadIdx.x;
    const int row0 = blockIdx.y * 128;
    const int col0 = blockIdx.x * 128;
    const int tx = tid & 15;
    const int ty = tid >> 4;
    const int lm = tid >> 2;
    const int lk = (tid & 3) * 4;

    const float* Ap = A + (size_t)(row0 + lm) * ND + lk;
    const float* Bp = W + (size_t)(col0 + lm) * ND + lk;

    ull acc[8][4];
#pragma unroll
    for (int i = 0; i < 8; i++)
#pragma unroll
        for (int j = 0; j < 4; j++) acc[i][j] = 0ull;

    float4 pa0, pa1, pb0, pb1;
    GEMM_LOAD(0);
    GEMM_STORE(0);
    GEMM_LOAD(1);        // prefetch kt=1 (overlaps the barrier)
    __syncthreads();

#pragma unroll 1
    for (int kt = 0; kt < 32; kt += 2) {
        GEMM_STORE(1);
        if (kt + 2 < 32) GEMM_LOAD(kt + 2);
        GEMM_COMPUTE(0);
        __syncthreads();
        if (kt + 2 < 32) {
            GEMM_STORE(0);
            if (kt + 3 < 32) GEMM_LOAD(kt + 3);
        }
        GEMM_COMPUTE(1);
        __syncthreads();
    }

    float bv[8];
#pragma unroll
    for (int j = 0; j < 8; j++) bv[j] = bias[col0 + tx * 8 + j];
#pragma unroll
    for (int i = 0; i < 8; i++) {
        float o[8];
        unpack2(acc[i][0], o[0], o[1]);
        unpack2(acc[i][1], o[2], o[3]);
        unpack2(acc[i][2], o[4], o[5]);
        unpack2(acc[i][3], o[6], o[7]);
#pragma unroll
        for (int j = 0; j < 8; j++) o[j] += bv[j];
        float* cp = g_h1 + (size_t)(row0 + ty * 8 + i) * NH + col0 + tx * 8;
        ((float4*)cp)[0] = make_float4(o[0], o[1], o[2], o[3]);
        ((float4*)cp)[1] = make_float4(o[4], o[5], o[6], o[7]);
    }
}

// ============================================================================
// block-wide reduction (blockDim multiple of 32, <= 256)
// ============================================================================
__device__ __forceinline__ float block_reduce_sum(float val) {
    __shared__ float sm[32];
    const int tid = threadIdx.x;
#pragma unroll
    for (int o = 16; o; o >>= 1) val += __shfl_down_sync(0xffffffffu, val, o);
    if ((tid & 31) == 0) sm[tid >> 5] = val;
    __syncthreads();
    if (tid < 32) {
        const int nw = (blockDim.x + 31) >> 5;
        float v = (tid < nw) ? sm[tid] : 0.f;
#pragma unroll
        for (int o = 4; o; o >>= 1) v += __shfl_down_sync(0xffffffffu, v, o);
        if (tid == 0) sm[0] = v;
    }
    __syncthreads();
    float r = sm[0];
    __syncthreads();
    return r;
}

// ============================================================================
// LN1 stats, WARP-PER-ROW: lane holds 8 float4 (32 values), shfl_xor butterfly
// reductions, zero block barriers. 8 rows per 256-thread block.
// ============================================================================
__global__ __launch_bounds__(256) void ln1_stats_kernel() {
    const int wid = threadIdx.x >> 5;           // 0..7
    const int lane = threadIdx.x & 31;
    const int row = blockIdx.x * 8 + wid;
    const float4* p = (const float4*)(g_h1 + (size_t)row * NH);

    float4 v[8];
#pragma unroll
    for (int j = 0; j < 8; j++) v[j] = p[lane + j * 32];

    float s = 0.f;
#pragma unroll
    for (int j = 0; j < 8; j++) s += (v[j].x + v[j].y) + (v[j].z + v[j].w);
#pragma unroll
    for (int o = 16; o; o >>= 1) s += __shfl_xor_sync(0xffffffffu, s, o);
    const float mean = s * (1.0f / NH);

    float sq = 0.f;
#pragma unroll
    for (int j = 0; j < 8; j++) {
        float d0 = v[j].x - mean, d1 = v[j].y - mean;
        float d2 = v[j].z - mean, d3 = v[j].w - mean;
        sq += (d0 * d0 + d1 * d1) + (d2 * d2 + d3 * d3);
    }
#pragma unroll
    for (int o = 16; o; o >>= 1) sq += __shfl_xor_sync(0xffffffffu, sq, o);
    const float inv = 1.0f / sqrtf(sq * (1.0f / NH) + 1e-5f);

    if (lane == 0) { g_mean[row] = mean; g_inv[row] = inv; }
}

// ============================================================================
// LIF layer 1 with inline LayerNorm, SOFTWARE-PIPELINED (R12-verified).
// ============================================================================
__global__ __launch_bounds__(128) void lif1_kernel(const float* __restrict__ g1,
                                                   const float* __restrict__ be1) {
    const int idx = blockIdx.x * 128 + threadIdx.x;   // NB*NH = 32768
    const int b = idx >> 10;
    const int h = idx & (NH - 1);
    const int tid = threadIdx.x;

    __shared__ float s_mean[NT];
    __shared__ float s_inv[NT];
#pragma unroll
    for (int t = tid; t < NT; t += 128) {
        s_mean[t] = g_mean[b * NT + t];
        s_inv[t]  = g_inv [b * NT + t];
    }
    __syncthreads();

    const float gh  = g1[h];
    const float beh = be1[h];
    const float* p = g_h1 + (size_t)b * NT * NH + h;
    unsigned char* q = g_s1 + (size_t)b * NT * NH + h;

    float xa[16], xb[16];
#pragma unroll
    for (int i = 0; i < 16; i++) xa[i] = p[(size_t)i * NH];

    float v = 0.f;
#pragma unroll 1
    for (int t0 = 0; t0 < NT; t0 += 32) {
#pragma unroll
        for (int i = 0; i < 16; i++) xb[i] = p[(size_t)(t0 + 16 + i) * NH];

        unsigned char sb[16];
#pragma unroll
        for (int i = 0; i < 16; i++) {
            float d = xa[i] - s_mean[t0 + i];
            float val = d * s_inv[t0 + i] * gh + beh;
            v = v + (val - v) * 0.5f;       // TAU = 2
            bool sp = (v >= 1.0f);          // V_TH = 1
            sb[i] = sp ? (unsigned char)1 : (unsigned char)0;
            v = sp ? 0.f : v;               // hard reset
        }
#pragma unroll
        for (int i = 0; i < 16; i++) q[(size_t)(t0 + i) * NH] = sb[i];

        if (t0 + 32 < NT) {
#pragma unroll
            for (int i = 0; i < 16; i++) xa[i] = p[(size_t)(t0 + 32 + i) * NH];
        }

#pragma unroll
        for (int i = 0; i < 16; i++) {
            float d = xb[i] - s_mean[t0 + 16 + i];
            float val = d * s_inv[t0 + 16 + i] * gh + beh;
            v = v + (val - v) * 0.5f;
            bool sp = (v >= 1.0f);
            sb[i] = sp ? (unsigned char)1 : (unsigned char)0;
            v = sp ? 0.f : v;
        }
#pragma unroll
        for (int i = 0; i < 16; i++) q[(size_t)(t0 + 16 + i) * NH] = sb[i];
    }
}

// ============================================================================
// fc2 (sparse gmem gather, L1-resident w2t) + fused LayerNorm2 (R4-verified).
// ============================================================================
__global__ __launch_bounds__(128) void fc2ln2_kernel(const float* __restrict__ b2,
                                                     const float* __restrict__ g2,
                                                     const float* __restrict__ be2) {
    const int row = blockIdx.x;
    const int tid = threadIdx.x;
    const unsigned char* srow = g_s1 + (size_t)row * NH;

    ull m8 = ((const ull*)srow)[tid];           // 8 spike bytes
    int c = __popcll(m8);
    int pre = c;
#pragma unroll
    for (int o = 1; o < 32; o <<= 1) {
        int n = __shfl_up_sync(0xffffffffu, pre, o);
        if ((tid & 31) >= o) pre += n;
    }
    __shared__ int wsum[4];
    __shared__ unsigned short list[NH];
    __shared__ int s_total;
    if ((tid & 31) == 31) wsum[tid >> 5] = pre;
    __syncthreads();
    int base = 0;
#pragma unroll
    for (int w = 0; w < 4; w++)
        if (w < (tid >> 5)) base += wsum[w];
    int off = base + pre - c;
#pragma unroll
    for (int k = 0; k < 8; k++)
        if ((m8 >> (8 * k)) & 1ull) list[off++] = (unsigned short)(tid * 8 + k);
    if (tid == 127) s_total = base + pre;
    __syncthreads();

    const int cnt = s_total;
    const float* wbase = g_w2t + tid * 4;
    float4 acc = make_float4(0.f, 0.f, 0.f, 0.f);
    int i = 0;
    for (; i + 4 <= cnt; i += 4) {
        int h0 = list[i], h1 = list[i + 1], h2 = list[i + 2], h3 = list[i + 3];
        float4 w0 = *(const float4*)(wbase + (size_t)h0 * ND);
        float4 w1 = *(const float4*)(wbase + (size_t)h1 * ND);
        float4 w2v = *(const float4*)(wbase + (size_t)h2 * ND);
        float4 w3 = *(const float4*)(wbase + (size_t)h3 * ND);
        acc.x += w0.x; acc.y += w0.y; acc.z += w0.z; acc.w += w0.w;
        acc.x += w1.x; acc.y += w1.y; acc.z += w1.z; acc.w += w1.w;
        acc.x += w2v.x; acc.y += w2v.y; acc.z += w2v.z; acc.w += w2v.w;
        acc.x += w3.x; acc.y += w3.y; acc.z += w3.z; acc.w += w3.w;
    }
    for (; i < cnt; i++) {
        float4 w0 = *(const float4*)(wbase + (size_t)list[i] * ND);
        acc.x += w0.x; acc.y += w0.y; acc.z += w0.z; acc.w += w0.w;
    }
    float4 bb = ((const float4*)b2)[tid];
    acc.x += bb.x; acc.y += bb.y; acc.z += bb.z; acc.w += bb.w;

    // ---- fused LayerNorm2 ----
    float s = (acc.x + acc.y) + (acc.z + acc.w);
    float total = block_reduce_sum(s);
    float mean = total * (1.0f / ND);
    float d0 = acc.x - mean, d1 = acc.y - mean, d2 = acc.z - mean, d3 = acc.w - mean;
    float sq = (d0 * d0 + d1 * d1) + (d2 * d2 + d3 * d3);
    float tot2 = block_reduce_sum(sq);
    float inv = 1.0f / sqrtf(tot2 * (1.0f / ND) + 1e-5f);
    float4 gg = ((const float4*)g2)[tid];
    float4 bv = ((const float4*)be2)[tid];
    float4 o;
    o.x = d0 * inv * gg.x + bv.x;
    o.y = d1 * inv * gg.y + bv.y;
    o.z = d2 * inv * gg.z + bv.z;
    o.w = d3 * inv * gg.w + bv.w;
    ((float4*)(g_y + (size_t)row * ND))[tid] = o;
}

// ============================================================================
// LIF layer 2 + residual, SOFTWARE-PIPELINED (R11-verified).
// ============================================================================
__global__ __launch_bounds__(64) void lif2_kernel(const float* __restrict__ x,
                                                  float* __restrict__ out) {
    const int idx = blockIdx.x * 64 + threadIdx.x;    // NB*ND = 16384
    const int b = idx >> 9;
    const int d = idx & (ND - 1);
    const float* py = g_y + (size_t)b * NT * ND + d;
    const float* px = x + (size_t)b * NT * ND + d;
    float* po = out + (size_t)b * NT * ND + d;

    float ya[16], xa[16], yb[16], xb[16];
#pragma unroll
    for (int i = 0; i < 16; i++) { ya[i] = py[(size_t)i * ND]; }
#pragma unroll
    for (int i = 0; i < 16; i++) { xa[i] = px[(size_t)i * ND]; }

    float v = 0.f;
#pragma unroll 1
    for (int t0 = 0; t0 < NT; t0 += 32) {
#pragma unroll
        for (int i = 0; i < 16; i++) yb[i] = py[(size_t)(t0 + 16 + i) * ND];
#pragma unroll
        for (int i = 0; i < 16; i++) xb[i] = px[(size_t)(t0 + 16 + i) * ND];

        float ob[16];
#pragma unroll
        for (int i = 0; i < 16; i++) {
            v = v + (ya[i] - v) * 0.5f;
            bool sp = (v >= 1.0f);
            ob[i] = xa[i] + (sp ? 1.0f : 0.0f);
            v = sp ? 0.f : v;
        }
#pragma unroll
        for (int i = 0; i < 16; i++) po[(size_t)(t0 + i) * ND] = ob[i];

        if (t0 + 32 < NT) {
#pragma unroll
            for (int i = 0; i < 16; i++) ya[i] = py[(size_t)(t0 + 32 + i) * ND];
#pragma unroll
            for (int i = 0; i < 16; i++) xa[i] = px[(size_t)(t0 + 32 + i) * ND];
        }

#pragma unroll
        for (int i = 0; i < 16; i++) {
            v = v + (yb[i] - v) * 0.5f;
            bool sp = (v >= 1.0f);
            ob[i] = xb[i] + (sp ? 1.0f : 0.0f);
            v = sp ? 0.f : v;
        }
#pragma unroll
        for (int i = 0; i < 16; i++) po[(size_t)(t0 + 16 + i) * ND] = ob[i];
    }
}

// ============================================================================
// w2 [D, H] -> g_w2t [H, D]
// ============================================================================
__global__ void transpose_kernel(const float* __restrict__ w2) {
    __shared__ float tile[32][33];
    const int h0 = blockIdx.x * 32;
    const int d0 = blockIdx.y * 32;
    tile[threadIdx.y][threadIdx.x] = w2[(size_t)(d0 + threadIdx.y) * NH + h0 + threadIdx.x];
    __syncthreads();
    g_w2t[(size_t)(h0 + threadIdx.y) * ND + d0 + threadIdx.x] = tile[threadIdx.x][threadIdx.y];
}

// ============================================================================
extern "C" void kernel_launch(void* const* d_in, const int* in_sizes, int n_in,
                              void* d_out, int out_size) {
    const float* x   = (const float*)d_in[0];
    const float* w1  = (const float*)d_in[1];
    const float* b1  = (const float*)d_in[2];
    const float* g1  = (const float*)d_in[3];
    const float* be1 = (const float*)d_in[4];
    const float* w2  = (const float*)d_in[5];
    const float* b2  = (const float*)d_in[6];
    const float* g2  = (const float*)d_in[7];
    const float* be2 = (const float*)d_in[8];
    float* out = (float*)d_out;

    transpose_kernel<<<dim3(NH / 32, ND / 32), dim3(32, 32)>>>(w2);
    gemm1_kernel<<<dim3(NH / 128, NM / 128), 256>>>(x, w1, b1);
    ln1_stats_kernel<<<NM / 8, 256>>>();
    lif1_kernel<<<(NB * NH) / 128, 128>>>(g1, be1);
    fc2ln2_kernel<<<NM, 128>>>(b2, g2, be2);
    lif2_kernel<<<(NB * ND) / 64, 64>>>(x, out);
}